// round 2
// baseline (speedup 1.0000x reference)
#include <cuda_runtime.h>
#include <math.h>
#include <stdint.h>

#define NB   16     // batch
#define CIN  64
#define CE   64
#define HIN  256
#define WIN  256
#define HOUT 128
#define WOUT 128

// ---------------- device scratch (no allocations allowed) ----------------
__device__ float d_pooled[NB][CIN];
__device__ int   d_count[4];
__device__ int   d_pair_b[4][2 * NB];
__device__ int   d_pair_slot[4][2 * NB];
__device__ float d_pair_wt[4][2 * NB];
__device__ float d_bnA[4][CE];
__device__ float d_bnB[4][CE];

// ---------------- kernel A: global average pool -------------------------
__global__ void pool_kernel(const float* __restrict__ x) {
    int c = blockIdx.x, b = blockIdx.y;
    const float4* p = (const float4*)(x + ((size_t)(b * CIN + c)) * (HIN * WIN));
    float s = 0.f;
    #pragma unroll 4
    for (int i = threadIdx.x; i < HIN * WIN / 4; i += 256) {
        float4 v = p[i];
        s += (v.x + v.y) + (v.z + v.w);
    }
    __shared__ float sm[256];
    sm[threadIdx.x] = s;
    __syncthreads();
    for (int o = 128; o > 0; o >>= 1) {
        if (threadIdx.x < o) sm[threadIdx.x] += sm[threadIdx.x + o];
        __syncthreads();
    }
    if (threadIdx.x == 0)
        d_pooled[b][c] = sm[0] * (1.0f / (HIN * WIN));
}

// ---------------- kernel B: gate + top2 + BN fold -----------------------
__global__ void gate_kernel(const float* __restrict__ gw, const float* __restrict__ gb,
                            const float* __restrict__ cb0, const float* __restrict__ cb1,
                            const float* __restrict__ cb2, const float* __restrict__ cb3,
                            const float* __restrict__ bns, const float* __restrict__ bnb,
                            const float* __restrict__ bnm, const float* __restrict__ bnv) {
    int t = threadIdx.x;
    if (t < 4) d_count[t] = 0;

    // fold conv bias + BN into alpha/beta per (expert, oc): 256 entries
    {
        int e = t >> 6, oc = t & 63;
        float inv = bns[e * CE + oc] * rsqrtf(bnv[e * CE + oc] + 1e-5f);
        const float* cb = (e == 0) ? cb0 : (e == 1) ? cb1 : (e == 2) ? cb2 : cb3;
        d_bnA[e][oc] = inv;
        d_bnB[e][oc] = cb[oc] * inv + bnb[e * CE + oc] - bnm[e * CE + oc] * inv;
    }

    __shared__ float logits[NB][4];
    if (t < NB * 4) {
        int b = t >> 2, e = t & 3;
        float s = gb[e];
        #pragma unroll
        for (int c = 0; c < CIN; c++) s += d_pooled[b][c] * gw[e * CIN + c];
        logits[b][e] = s;
    }
    __syncthreads();   // also orders the d_count zeroing before atomics below

    if (t < NB) {
        int b = t;
        float g[4];
        float mx = -1e30f;
        #pragma unroll
        for (int e = 0; e < 4; e++) { g[e] = logits[b][e]; mx = fmaxf(mx, g[e]); }
        float sum = 0.f;
        #pragma unroll
        for (int e = 0; e < 4; e++) { g[e] = expf(g[e] - mx); sum += g[e]; }
        #pragma unroll
        for (int e = 0; e < 4; e++) g[e] /= sum;
        // top-2, first-index wins ties (lax.top_k semantics)
        int i1 = 0;
        #pragma unroll
        for (int e = 1; e < 4; e++) if (g[e] > g[i1]) i1 = e;
        int i2 = -1;
        #pragma unroll
        for (int e = 0; e < 4; e++) {
            if (e == i1) continue;
            if (i2 < 0 || g[e] > g[i2]) i2 = e;
        }
        float norm = g[i1] + g[i2] + 1e-8f;
        float w1 = g[i1] / norm, w2 = g[i2] / norm;
        int p1 = atomicAdd(&d_count[i1], 1);
        d_pair_b[i1][p1] = b; d_pair_slot[i1][p1] = 0; d_pair_wt[i1][p1] = w1;
        int p2 = atomicAdd(&d_count[i2], 1);
        d_pair_b[i2][p2] = b; d_pair_slot[i2][p2] = 1; d_pair_wt[i2][p2] = w2;
    }
}

// ---------------- kernel C: expert conv as implicit GEMM -----------------
// One block: 64 oc x 64 spatial (one output row segment), K = CIN*KS*KS.
// grid: x = 2 (ox tiles of 64), y = 128 (oy), z = 32 (pair slot; early-exit)
__device__ __forceinline__ float gelu_exact(float v) {
    return 0.5f * v * (1.0f + erff(v * 0.70710678118654752440f));
}

template <int KS, int DIL>
__global__ void __launch_bounds__(256, 4)
conv_kernel(const float* __restrict__ x, const float* __restrict__ w,
            int expert, float* __restrict__ out) {
    int z = blockIdx.z;
    if (z >= d_count[expert]) return;

    const int b    = d_pair_b[expert][z];
    const int slot = d_pair_slot[expert][z];
    const float wt = d_pair_wt[expert][z];
    const int oy   = blockIdx.y;
    const int oxb  = blockIdx.x * 64;

    constexpr int K   = CIN * KS * KS;
    constexpr int PAD = DIL * (KS - 1) / 2;

    __shared__ __align__(16) float As[2][16][64];  // [buf][kk][oc]
    __shared__ __align__(16) float Bs[2][16][64];  // [buf][kk][sp]

    const int tid = threadIdx.x;
    // compute roles
    const int ty = tid >> 4;   // oc group  (0..15) -> oc = ty*4 + i
    const int tx = tid & 15;   // sp group  (0..15) -> sp = tx*4 + j
    // gather roles
    const int gkk = tid >> 4;  // 0..15 : Bs row
    const int gsg = tid & 15;  // 0..15 : 4 consecutive sp
    const int aoc = tid & 63;  // As: oc
    const int aj  = tid >> 6;  // As: which 4-group of kk

    const float* wbase = w + (size_t)aoc * K + aj * 4;
    const float* xb    = x + (size_t)b * CIN * HIN * WIN;

    float acc[4][4];
    #pragma unroll
    for (int i = 0; i < 4; i++)
        #pragma unroll
        for (int j = 0; j < 4; j++) acc[i][j] = 0.f;

    // per-chunk gather: returns staged registers for chunk starting at kb
    auto load_regs = [&](int kb, float4& wv, float& v0, float& v1, float& v2, float& v3) {
        wv = *(const float4*)(wbase + kb);
        int kidx = kb + gkk;
        int cin  = kidx / (KS * KS);
        int r    = kidx - cin * (KS * KS);
        int kh   = r / KS;
        int kw   = r - kh * KS;
        int iy   = 2 * oy + DIL * kh - PAD;
        bool vy  = ((unsigned)iy < (unsigned)HIN);
        const float* xrow = xb + ((size_t)cin * HIN + (vy ? iy : 0)) * WIN;
        int ix0 = 2 * (oxb + gsg * 4) + DIL * kw - PAD;
        v0 = (vy && (unsigned)(ix0)     < (unsigned)WIN) ? __ldg(xrow + ix0)     : 0.f;
        v1 = (vy && (unsigned)(ix0 + 2) < (unsigned)WIN) ? __ldg(xrow + ix0 + 2) : 0.f;
        v2 = (vy && (unsigned)(ix0 + 4) < (unsigned)WIN) ? __ldg(xrow + ix0 + 4) : 0.f;
        v3 = (vy && (unsigned)(ix0 + 6) < (unsigned)WIN) ? __ldg(xrow + ix0 + 6) : 0.f;
    };
    auto store_smem = [&](int buf, const float4& wv, float v0, float v1, float v2, float v3) {
        As[buf][aj * 4 + 0][aoc] = wv.x;
        As[buf][aj * 4 + 1][aoc] = wv.y;
        As[buf][aj * 4 + 2][aoc] = wv.z;
        As[buf][aj * 4 + 3][aoc] = wv.w;
        Bs[buf][gkk][gsg * 4 + 0] = v0;
        Bs[buf][gkk][gsg * 4 + 1] = v1;
        Bs[buf][gkk][gsg * 4 + 2] = v2;
        Bs[buf][gkk][gsg * 4 + 3] = v3;
    };

    // prologue: fill buffer 0
    {
        float4 wv; float v0, v1, v2, v3;
        load_regs(0, wv, v0, v1, v2, v3);
        store_smem(0, wv, v0, v1, v2, v3);
    }
    __syncthreads();

    int buf = 0;
    for (int kb = 0; kb < K; kb += 16) {
        // prefetch next chunk into the other buffer (no sync needed before
        // writing buf^1: nobody reads it until after the barrier below)
        if (kb + 16 < K) {
            float4 wv; float v0, v1, v2, v3;
            load_regs(kb + 16, wv, v0, v1, v2, v3);
            store_smem(buf ^ 1, wv, v0, v1, v2, v3);
        }

        // ---- compute from current buffer ----
        #pragma unroll
        for (int kk = 0; kk < 16; kk++) {
            float4 a  = *(const float4*)&As[buf][kk][ty * 4];
            float4 bb = *(const float4*)&Bs[buf][kk][tx * 4];
            acc[0][0] += a.x * bb.x; acc[0][1] += a.x * bb.y;
            acc[0][2] += a.x * bb.z; acc[0][3] += a.x * bb.w;
            acc[1][0] += a.y * bb.x; acc[1][1] += a.y * bb.y;
            acc[1][2] += a.y * bb.z; acc[1][3] += a.y * bb.w;
            acc[2][0] += a.z * bb.x; acc[2][1] += a.z * bb.y;
            acc[2][2] += a.z * bb.z; acc[2][3] += a.z * bb.w;
            acc[3][0] += a.w * bb.x; acc[3][1] += a.w * bb.y;
            acc[3][2] += a.w * bb.z; acc[3][3] += a.w * bb.w;
        }

        // one barrier per chunk: separates reads of buf (this iter) from
        // writes to buf (next iter) and publishes buf^1 for the next compute
        __syncthreads();
        buf ^= 1;
    }

    // ---- epilogue: BN (folded) + exact GELU + gate weight ----
    #pragma unroll
    for (int i = 0; i < 4; i++) {
        int oc = ty * 4 + i;
        float alpha = d_bnA[expert][oc];
        float beta  = d_bnB[expert][oc];
        float4 o;
        float t0 = acc[i][0] * alpha + beta;
        float t1 = acc[i][1] * alpha + beta;
        float t2 = acc[i][2] * alpha + beta;
        float t3 = acc[i][3] * alpha + beta;
        o.x = gelu_exact(t0) * wt;
        o.y = gelu_exact(t1) * wt;
        o.z = gelu_exact(t2) * wt;
        o.w = gelu_exact(t3) * wt;
        float* op = out + ((((size_t)b * 128) + slot * 64 + oc) * HOUT + oy) * WOUT
                        + oxb + tx * 4;
        *(float4*)op = o;
    }
}

// ---------------- launch -------------------------------------------------
extern "C" void kernel_launch(void* const* d_in, const int* in_sizes, int n_in,
                              void* d_out, int out_size) {
    const float* x   = (const float*)d_in[0];
    const float* w0  = (const float*)d_in[1];
    const float* cb0 = (const float*)d_in[2];
    const float* w1  = (const float*)d_in[3];
    const float* cb1 = (const float*)d_in[4];
    const float* w2  = (const float*)d_in[5];
    const float* cb2 = (const float*)d_in[6];
    const float* w3  = (const float*)d_in[7];
    const float* cb3 = (const float*)d_in[8];
    const float* bns = (const float*)d_in[9];
    const float* bnb = (const float*)d_in[10];
    const float* bnm = (const float*)d_in[11];
    const float* bnv = (const float*)d_in[12];
    const float* gw  = (const float*)d_in[13];
    const float* gb  = (const float*)d_in[14];
    float* out = (float*)d_out;

    pool_kernel<<<dim3(CIN, NB), 256>>>(x);
    gate_kernel<<<1, 256>>>(gw, gb, cb0, cb1, cb2, cb3, bns, bnb, bnm, bnv);

    dim3 grid(WOUT / 64, HOUT, 2 * NB);
    conv_kernel<3, 1><<<grid, 256>>>(x, w0, 0, out);
    conv_kernel<5, 2><<<grid, 256>>>(x, w1, 1, out);
    conv_kernel<7, 3><<<grid, 256>>>(x, w2, 2, out);
    conv_kernel<9, 4><<<grid, 256>>>(x, w3, 3, out);
}

// round 4
// speedup vs baseline: 1.4963x; 1.4963x over previous
#include <cuda_runtime.h>
#include <math.h>
#include <stdint.h>

#define NB   16     // batch
#define CIN  64
#define CE   64
#define HIN  256
#define WIN  256
#define HOUT 128
#define WOUT 128

// ---------------- device scratch (no allocations allowed) ----------------
__device__ float d_pooled[NB][CIN];
__device__ int   d_count[4];
__device__ int   d_pair_b[4][2 * NB];
__device__ int   d_pair_slot[4][2 * NB];
__device__ float d_pair_wt[4][2 * NB];
__device__ float d_bnA[4][CE];
__device__ float d_bnB[4][CE];
// transposed weights wT[k][oc] per expert, packed: K0=576,K1=1600,K2=3136,K3=5184
__device__ float d_wT[(576 + 1600 + 3136 + 5184) * 64];

// ---------------- kernel A: global average pool -------------------------
__global__ void pool_kernel(const float* __restrict__ x) {
    int c = blockIdx.x, b = blockIdx.y;
    const float4* p = (const float4*)(x + ((size_t)(b * CIN + c)) * (HIN * WIN));
    float s = 0.f;
    #pragma unroll 4
    for (int i = threadIdx.x; i < HIN * WIN / 4; i += 256) {
        float4 v = p[i];
        s += (v.x + v.y) + (v.z + v.w);
    }
    __shared__ float sm[256];
    sm[threadIdx.x] = s;
    __syncthreads();
    for (int o = 128; o > 0; o >>= 1) {
        if (threadIdx.x < o) sm[threadIdx.x] += sm[threadIdx.x + o];
        __syncthreads();
    }
    if (threadIdx.x == 0)
        d_pooled[b][c] = sm[0] * (1.0f / (HIN * WIN));
}

// ---------------- kernel B: gate + top2 + BN fold -----------------------
__global__ void gate_kernel(const float* __restrict__ gw, const float* __restrict__ gb,
                            const float* __restrict__ cb0, const float* __restrict__ cb1,
                            const float* __restrict__ cb2, const float* __restrict__ cb3,
                            const float* __restrict__ bns, const float* __restrict__ bnb,
                            const float* __restrict__ bnm, const float* __restrict__ bnv) {
    int t = threadIdx.x;
    if (t < 4) d_count[t] = 0;

    {   // fold conv bias + BN into alpha/beta per (expert, oc)
        int e = t >> 6, oc = t & 63;
        float inv = bns[e * CE + oc] * rsqrtf(bnv[e * CE + oc] + 1e-5f);
        const float* cb = (e == 0) ? cb0 : (e == 1) ? cb1 : (e == 2) ? cb2 : cb3;
        d_bnA[e][oc] = inv;
        d_bnB[e][oc] = cb[oc] * inv + bnb[e * CE + oc] - bnm[e * CE + oc] * inv;
    }

    __shared__ float logits[NB][4];
    if (t < NB * 4) {
        int b = t >> 2, e = t & 3;
        float s = gb[e];
        #pragma unroll
        for (int c = 0; c < CIN; c++) s += d_pooled[b][c] * gw[e * CIN + c];
        logits[b][e] = s;
    }
    __syncthreads();

    if (t < NB) {
        int b = t;
        float g[4];
        float mx = -1e30f;
        #pragma unroll
        for (int e = 0; e < 4; e++) { g[e] = logits[b][e]; mx = fmaxf(mx, g[e]); }
        float sum = 0.f;
        #pragma unroll
        for (int e = 0; e < 4; e++) { g[e] = expf(g[e] - mx); sum += g[e]; }
        #pragma unroll
        for (int e = 0; e < 4; e++) g[e] /= sum;
        int i1 = 0;
        #pragma unroll
        for (int e = 1; e < 4; e++) if (g[e] > g[i1]) i1 = e;
        int i2 = -1;
        #pragma unroll
        for (int e = 0; e < 4; e++) {
            if (e == i1) continue;
            if (i2 < 0 || g[e] > g[i2]) i2 = e;
        }
        float norm = g[i1] + g[i2] + 1e-8f;
        float w1 = g[i1] / norm, w2 = g[i2] / norm;
        int p1 = atomicAdd(&d_count[i1], 1);
        d_pair_b[i1][p1] = b; d_pair_slot[i1][p1] = 0; d_pair_wt[i1][p1] = w1;
        int p2 = atomicAdd(&d_count[i2], 1);
        d_pair_b[i2][p2] = b; d_pair_slot[i2][p2] = 1; d_pair_wt[i2][p2] = w2;
    }
}

// ---------------- weight transpose: w[oc][k] -> wT[k][oc] ----------------
// K always a multiple of 32; OC=64. grid (K/32, 2), block (32, 8).
__global__ void transpose_w_kernel(const float* __restrict__ w, int wOff, int K) {
    __shared__ float t[32][33];
    int kb = blockIdx.x * 32, ob = blockIdx.y * 32;
    for (int r = threadIdx.y; r < 32; r += 8)
        t[r][threadIdx.x] = w[(size_t)(ob + r) * K + kb + threadIdx.x];
    __syncthreads();
    for (int r = threadIdx.y; r < 32; r += 8)
        d_wT[wOff + (size_t)(kb + r) * 64 + ob + threadIdx.x] = t[threadIdx.x][r];
}

// ---------------- kernel C: expert conv, staged-row implicit GEMM --------
// Block: 64 oc x 128 sp (full output row), one oy. 256 threads, micro 8oc x 4sp.
// K loop chunked over CCH input channels; per chunk stage CCH*KS raw x rows
// (even/odd split) + CCH*KS*KS weight rows (cp.async), double buffered.
__device__ __forceinline__ float gelu_exact(float v) {
    return 0.5f * v * (1.0f + erff(v * 0.70710678118654752440f));
}

template <int KS, int DIL, int CCH>
__global__ void __launch_bounds__(256, 2)
conv_kernel(const float* __restrict__ x, int wOff, int expert,
            float* __restrict__ out) {
    constexpr int R    = CCH * KS;                 // x rows per chunk
    constexpr int PAD  = DIL * (KS - 1) / 2;
    constexpr int Wh   = (128 + PAD + 3) & ~3;     // half-row length, 16B-aligned
    constexpr int ASZ  = CCH * KS * KS * 64;       // weight floats per chunk
    constexpr int XSZ  = R * 2 * Wh;               // x floats per chunk
    constexpr int BUF  = ASZ + XSZ;
    constexpr int NCH  = CIN / CCH;                // chunks
    constexpr int N2   = (R * 128 + 255) / 256;    // float2 x-loads per thread

    int z = blockIdx.y;
    if (z >= d_count[expert]) return;
    const int   b    = d_pair_b[expert][z];
    const int   slot = d_pair_slot[expert][z];
    const float wt   = d_pair_wt[expert][z];
    const int   oy   = blockIdx.x;

    extern __shared__ __align__(16) float sm[];
    const int tid = threadIdx.x;
    const int ty  = tid >> 5;        // 0..7  -> oc = ty*8 + i
    const int tx  = tid & 31;        // 0..31 -> sp = tx + 32*j

    const float* xb   = x + (size_t)b * CIN * HIN * WIN;
    const float* wTe  = d_wT + wOff;

    float acc[8][4];
    #pragma unroll
    for (int i = 0; i < 8; i++)
        #pragma unroll
        for (int j = 0; j < 4; j++) acc[i][j] = 0.f;

    float2 xr[N2];

    // ---- issue chunk ch into buffer bufIdx: cp.async weights + LDG x->regs
    auto issue_chunk = [&](int ch, int bufIdx) {
        float* As_ = sm + bufIdx * BUF;
        const float4* wsrc = (const float4*)(wTe + (size_t)ch * ASZ);
        uint32_t sA = (uint32_t)__cvta_generic_to_shared(As_);
        for (int f = tid; f < ASZ / 4; f += 256) {
            asm volatile("cp.async.ca.shared.global [%0], [%1], 16;\n"
                         :: "r"(sA + f * 16), "l"(wsrc + f));
        }
        asm volatile("cp.async.commit_group;\n");
        #pragma unroll
        for (int q = 0; q < N2; q++) {
            int s = tid + q * 256;
            float2 v = make_float2(0.f, 0.f);
            if (s < R * 128) {
                int rr = s >> 7, j = s & 127;
                int kh = rr % KS, cin = ch * CCH + rr / KS;
                int iy = 2 * oy + DIL * kh - PAD;
                if ((unsigned)iy < (unsigned)HIN)
                    v = ((const float2*)(xb + ((size_t)cin * HIN + iy) * WIN))[j];
            }
            xr[q] = v;
        }
    };
    // ---- scatter x regs into even/odd arrays of buffer bufIdx
    auto store_x = [&](int bufIdx) {
        float* xs = sm + bufIdx * BUF + ASZ;
        #pragma unroll
        for (int q = 0; q < N2; q++) {
            int s = tid + q * 256;
            if (s < R * 128) {
                int rr = s >> 7, j = s & 127;
                int r0 = 2 * j + PAD;  // slot for v.x; v.y -> r0+1
                xs[(rr * 2 + (r0 & 1)) * Wh + (r0 >> 1)]             = xr[q].x;
                xs[(rr * 2 + ((r0 + 1) & 1)) * Wh + ((r0 + 1) >> 1)] = xr[q].y;
            }
        }
    };

    // ---- prologue: zero pad slots (both buffers, written once), stage chunk 0
    for (int s = tid; s < 2 * R * 2 * PAD; s += 256) {
        int bufIdx = s >= R * 2 * PAD;
        int s2 = s - bufIdx * R * 2 * PAD;
        int rr = s2 / (2 * PAD), q2 = s2 % (2 * PAD);
        int r = (q2 < PAD) ? q2 : (256 + PAD + (q2 - PAD));
        sm[bufIdx * BUF + ASZ + (rr * 2 + (r & 1)) * Wh + (r >> 1)] = 0.f;
    }
    issue_chunk(0, 0);
    asm volatile("cp.async.wait_group 0;\n");
    store_x(0);
    __syncthreads();

    for (int ch = 0; ch < NCH; ch++) {
        const int bufIdx = ch & 1;
        const bool has_next = (ch + 1 < NCH);
        if (has_next) issue_chunk(ch + 1, bufIdx ^ 1);

        // ---- compute from current buffer ----
        const float* As_ = sm + bufIdx * BUF;
        const float* xs  = As_ + ASZ;
        for (int rr = 0; rr < R; rr++) {
            const float* arow = As_ + rr * KS * 64 + ty * 8;
            const float* xrow = xs + rr * 2 * Wh;
            #pragma unroll
            for (int kw = 0; kw < KS; kw++) {
                const int c = DIL * kw;
                const float* bp = xrow + (c & 1) * Wh + (c >> 1) + tx;
                float4 a0 = *(const float4*)(arow + kw * 64);
                float4 a1 = *(const float4*)(arow + kw * 64 + 4);
                float b0 = bp[0], b1 = bp[32], b2 = bp[64], b3 = bp[96];
                acc[0][0] += a0.x * b0; acc[0][1] += a0.x * b1; acc[0][2] += a0.x * b2; acc[0][3] += a0.x * b3;
                acc[1][0] += a0.y * b0; acc[1][1] += a0.y * b1; acc[1][2] += a0.y * b2; acc[1][3] += a0.y * b3;
                acc[2][0] += a0.z * b0; acc[2][1] += a0.z * b1; acc[2][2] += a0.z * b2; acc[2][3] += a0.z * b3;
                acc[3][0] += a0.w * b0; acc[3][1] += a0.w * b1; acc[3][2] += a0.w * b2; acc[3][3] += a0.w * b3;
                acc[4][0] += a1.x * b0; acc[4][1] += a1.x * b1; acc[4][2] += a1.x * b2; acc[4][3] += a1.x * b3;
                acc[5][0] += a1.y * b0; acc[5][1] += a1.y * b1; acc[5][2] += a1.y * b2; acc[5][3] += a1.y * b3;
                acc[6][0] += a1.z * b0; acc[6][1] += a1.z * b1; acc[6][2] += a1.z * b2; acc[6][3] += a1.z * b3;
                acc[7][0] += a1.w * b0; acc[7][1] += a1.w * b1; acc[7][2] += a1.w * b2; acc[7][3] += a1.w * b3;
            }
        }

        if (has_next) {
            store_x(bufIdx ^ 1);
            asm volatile("cp.async.wait_group 0;\n");
        }
        __syncthreads();
    }

    // ---- epilogue: folded BN + exact GELU + gate weight ----
    #pragma unroll
    for (int i = 0; i < 8; i++) {
        int oc = ty * 8 + i;
        float alpha = d_bnA[expert][oc];
        float beta  = d_bnB[expert][oc];
        float* op = out + ((((size_t)b * 128) + slot * 64 + oc) * HOUT + oy) * WOUT + tx;
        #pragma unroll
        for (int j = 0; j < 4; j++) {
            float t = acc[i][j] * alpha + beta;
            op[32 * j] = gelu_exact(t) * wt;
        }
    }
}

// ---------------- launch -------------------------------------------------
extern "C" void kernel_launch(void* const* d_in, const int* in_sizes, int n_in,
                              void* d_out, int out_size) {
    const float* x   = (const float*)d_in[0];
    const float* w0  = (const float*)d_in[1];
    const float* cb0 = (const float*)d_in[2];
    const float* w1  = (const float*)d_in[3];
    const float* cb1 = (const float*)d_in[4];
    const float* w2  = (const float*)d_in[5];
    const float* cb2 = (const float*)d_in[6];
    const float* w3  = (const float*)d_in[7];
    const float* cb3 = (const float*)d_in[8];
    const float* bns = (const float*)d_in[9];
    const float* bnb = (const float*)d_in[10];
    const float* bnm = (const float*)d_in[11];
    const float* bnv = (const float*)d_in[12];
    const float* gw  = (const float*)d_in[13];
    const float* gb  = (const float*)d_in[14];
    float* out = (float*)d_out;

    // wT packing offsets (floats): K = 576, 1600, 3136, 5184
    const int K0 = 576, K1 = 1600, K2 = 3136, K3 = 5184;
    const int off0 = 0;
    const int off1 = off0 + K0 * 64;
    const int off2 = off1 + K1 * 64;
    const int off3 = off2 + K2 * 64;

    // dynamic smem sizes (bytes) = 2 * BUF * 4  (computed per template params)
    auto smemBytes = [](int KS, int DIL, int CCH) {
        int R = CCH * KS, PAD = DIL * (KS - 1) / 2;
        int Wh = (128 + PAD + 3) & ~3;
        int BUF = CCH * KS * KS * 64 + R * 2 * Wh;
        return 2 * BUF * 4;
    };
    int s0 = smemBytes(3, 1, 4), s1 = smemBytes(5, 2, 2);
    int s2 = smemBytes(7, 3, 1), s3 = smemBytes(9, 4, 1);
    // unconditional (no static guards): immediate APIs, not stream-captured ops
    cudaFuncSetAttribute(conv_kernel<3, 1, 4>, cudaFuncAttributeMaxDynamicSharedMemorySize, s0);
    cudaFuncSetAttribute(conv_kernel<5, 2, 2>, cudaFuncAttributeMaxDynamicSharedMemorySize, s1);
    cudaFuncSetAttribute(conv_kernel<7, 3, 1>, cudaFuncAttributeMaxDynamicSharedMemorySize, s2);
    cudaFuncSetAttribute(conv_kernel<9, 4, 1>, cudaFuncAttributeMaxDynamicSharedMemorySize, s3);

    pool_kernel<<<dim3(CIN, NB), 256>>>(x);
    gate_kernel<<<1, 256>>>(gw, gb, cb0, cb1, cb2, cb3, bns, bnb, bnm, bnv);

    transpose_w_kernel<<<dim3(K0 / 32, 2), dim3(32, 8)>>>(w0, off0, K0);
    transpose_w_kernel<<<dim3(K1 / 32, 2), dim3(32, 8)>>>(w1, off1, K1);
    transpose_w_kernel<<<dim3(K2 / 32, 2), dim3(32, 8)>>>(w2, off2, K2);
    transpose_w_kernel<<<dim3(K3 / 32, 2), dim3(32, 8)>>>(w3, off3, K3);

    dim3 grid(HOUT, 2 * NB);
    conv_kernel<3, 1, 4><<<grid, 256, s0>>>(x, off0, 0, out);
    conv_kernel<5, 2, 2><<<grid, 256, s1>>>(x, off1, 1, out);
    conv_kernel<7, 3, 1><<<grid, 256, s2>>>(x, off2, 2, out);
    conv_kernel<9, 4, 1><<<grid, 256, s3>>>(x, off3, 3, out);
}